// round 3
// baseline (speedup 1.0000x reference)
#include <cuda_runtime.h>
#include <cuda_bf16.h>

// CollisionRegularizer: mean over (B,N,N) of relu(R - dist)^2, diagonal masked.
// B=2, N=8192, xyz float32 (B,N,3). Output: 1 float (the mean).
//
// Strategy:
//  - Triangular tile-pairs (tj >= ti), off-diagonal tiles weighted x2.
//  - Branchless inner loop: sqrt.approx(0)=0 makes i==j contribute exactly R^2,
//    subtracted analytically at the end (B*N*R^2).
//  - f32x2 packed math (2 j-points per 64-bit reg) for the squared distance.
//  - j-tile stored NEGATED in shared (SoA) so subs become add.rn.f32x2.
//  - Deterministic: per-block partials -> fixed-order tree reduction kernel.

#define RADIUS 0.1f
#define NPTS   8192
#define NBATCH 2
#define TILE   512
#define THREADS 128
#define MI     4            // i-points per thread (TILE = THREADS*MI)
#define NTILES (NPTS / TILE)             // 16
#define NPAIRT (NTILES * (NTILES + 1) / 2)  // 136 tile-pairs per batch
#define NPART  (NBATCH * NPAIRT)            // 272 partials

typedef unsigned long long u64;

__device__ __forceinline__ u64 pack2(float lo, float hi) {
    u64 r; asm("mov.b64 %0, {%1, %2};" : "=l"(r) : "f"(lo), "f"(hi)); return r;
}
__device__ __forceinline__ void unpack2(u64 v, float& lo, float& hi) {
    asm("mov.b64 {%0, %1}, %2;" : "=f"(lo), "=f"(hi) : "l"(v));
}
__device__ __forceinline__ u64 add2(u64 a, u64 b) {
    u64 r; asm("add.rn.f32x2 %0, %1, %2;" : "=l"(r) : "l"(a), "l"(b)); return r;
}
__device__ __forceinline__ u64 mul2(u64 a, u64 b) {
    u64 r; asm("mul.rn.f32x2 %0, %1, %2;" : "=l"(r) : "l"(a), "l"(b)); return r;
}
__device__ __forceinline__ u64 fma2(u64 a, u64 b, u64 c) {
    u64 r; asm("fma.rn.f32x2 %0, %1, %2, %3;" : "=l"(r) : "l"(a), "l"(b), "l"(c)); return r;
}
__device__ __forceinline__ float sqrt_approx(float x) {
    float r; asm("sqrt.approx.f32 %0, %1;" : "=f"(r) : "f"(x)); return r;
}

__device__ float g_part[NPART];

__global__ __launch_bounds__(THREADS)
void collreg_pair_kernel(const float* __restrict__ xyz) {
    __shared__ __align__(16) float sx[TILE];
    __shared__ __align__(16) float sy[TILE];
    __shared__ __align__(16) float sz[TILE];
    __shared__ float red[THREADS];

    const int tid = threadIdx.x;
    const int b   = blockIdx.y;

    // Decode linear tile-pair index k -> (ti, tj), tj >= ti.
    int k = blockIdx.x;
    int ti = 0, rem = k;
    while (rem >= NTILES - ti) { rem -= NTILES - ti; ti++; }
    const int tj = ti + rem;

    const float* base = xyz + (size_t)b * NPTS * 3;

    // Load j tile (negated) into SoA shared arrays. 512 pts * 3 floats.
    for (int t = tid; t < TILE; t += THREADS) {
        const int j = tj * TILE + t;
        sx[t] = -base[j * 3 + 0];
        sy[t] = -base[j * 3 + 1];
        sz[t] = -base[j * 3 + 2];
    }
    __syncthreads();

    // Each thread owns MI i-points (strided for coalesced loads),
    // each coordinate replicated into both f32x2 halves.
    u64 xip[MI], yip[MI], zip[MI];
    float acc0[MI], acc1[MI];
#pragma unroll
    for (int m = 0; m < MI; m++) {
        const int i = ti * TILE + tid + m * THREADS;
        const float x = base[i * 3 + 0];
        const float y = base[i * 3 + 1];
        const float z = base[i * 3 + 2];
        xip[m] = pack2(x, x);
        yip[m] = pack2(y, y);
        zip[m] = pack2(z, z);
        acc0[m] = 0.0f;
        acc1[m] = 0.0f;
    }

    const u64* sx2 = reinterpret_cast<const u64*>(sx);
    const u64* sy2 = reinterpret_cast<const u64*>(sy);
    const u64* sz2 = reinterpret_cast<const u64*>(sz);

#pragma unroll 4
    for (int jh = 0; jh < TILE / 2; jh++) {
        const u64 njx = sx2[jh];   // (-xj0, -xj1) packed, LDS.64 broadcast
        const u64 njy = sy2[jh];
        const u64 njz = sz2[jh];
#pragma unroll
        for (int m = 0; m < MI; m++) {
            u64 dx = add2(xip[m], njx);
            u64 dy = add2(yip[m], njy);
            u64 dz = add2(zip[m], njz);
            u64 sq = mul2(dx, dx);
            sq = fma2(dy, dy, sq);
            sq = fma2(dz, dz, sq);
            float s0, s1;
            unpack2(sq, s0, s1);
            const float d0 = sqrt_approx(s0);
            const float t0 = fmaxf(RADIUS - d0, 0.0f);
            acc0[m] = fmaf(t0, t0, acc0[m]);
            const float d1 = sqrt_approx(s1);
            const float t1 = fmaxf(RADIUS - d1, 0.0f);
            acc1[m] = fmaf(t1, t1, acc1[m]);
        }
    }

    // Per-thread total, then deterministic block tree reduction.
    float tot = 0.0f;
#pragma unroll
    for (int m = 0; m < MI; m++) tot += acc0[m] + acc1[m];

    red[tid] = tot;
    __syncthreads();
#pragma unroll
    for (int s = THREADS / 2; s > 0; s >>= 1) {
        if (tid < s) red[tid] += red[tid + s];
        __syncthreads();
    }
    if (tid == 0) {
        const float w = (ti == tj) ? 1.0f : 2.0f;
        g_part[b * NPAIRT + blockIdx.x] = red[0] * w;
    }
}

__global__ void collreg_reduce_kernel(float* __restrict__ out) {
    __shared__ float red[256];
    const int tid = threadIdx.x;
    float v = 0.0f;
    for (int i = tid; i < NPART; i += 256) v += g_part[i];
    red[tid] = v;
    __syncthreads();
#pragma unroll
    for (int s = 128; s > 0; s >>= 1) {
        if (tid < s) red[tid] += red[tid + s];
        __syncthreads();
    }
    if (tid == 0) {
        // Subtract the analytic diagonal contribution (each i==i pair added
        // exactly (RADIUS - sqrt.approx(0))^2 = RADIUS^2).
        const float diag = (float)(NBATCH * NPTS) * (RADIUS * RADIUS);
        const float total = red[0] - diag;
        out[0] = total / ((float)NBATCH * (float)NPTS * (float)NPTS);
    }
}

extern "C" void kernel_launch(void* const* d_in, const int* in_sizes, int n_in,
                              void* d_out, int out_size) {
    const float* xyz = (const float*)d_in[0];
    float* out = (float*)d_out;
    (void)in_sizes; (void)n_in; (void)out_size;

    dim3 grid(NPAIRT, NBATCH);
    collreg_pair_kernel<<<grid, THREADS>>>(xyz);
    collreg_reduce_kernel<<<1, 256>>>(out);
}